// round 14
// baseline (speedup 1.0000x reference)
#include <cuda_runtime.h>
#include <cstdint>
#include <math.h>

// Problem constants: W=num_walks=10, L=walk_length=10, D=64 neighbors.
#define W_WALKS 10
#define L_STEPS 10
#define DNB 64
#define FULLMASK 0xFFFFFFFFu

#define EPSf 1e-10f
#define REL_GAP 1e-4f          // relative guard band (fast errors ~3e-5)
// masked surrogate bound: r_masked = c/e <= c*8.39e6; widened to absorb the
// ~2% fixed-point error in S.
#define MASKED_C_MULT 1.0e7f
#define LOG2E10 14.4269504089f // 10 * log2(e)
#define FP_SCALE 33554432.0f   // 2^25
#define FP_INV   2.9802322387695312e-8f // 2^-25
#define WALK_BATCH 4u

struct StepKeys {
    unsigned a[L_STEPS];
    unsigned b[L_STEPS];
};

// Persistent-warp work queue.
__device__ unsigned g_walk_ctr;

__global__ void reset_ctr_kernel() { g_walk_ctr = 0u; }

// ---------------------------------------------------------------------------
// Threefry-2x32 (20 rounds), matching jax._src.prng.threefry2x32 exactly.
// ---------------------------------------------------------------------------
__host__ __device__ __forceinline__ void threefry2x32(
    unsigned k0, unsigned k1, unsigned x0, unsigned x1,
    unsigned& o0, unsigned& o1)
{
    unsigned k2 = k0 ^ k1 ^ 0x1BD11BDAu;
    x0 += k0; x1 += k1;
#if defined(__CUDA_ARCH__)
#define TF_ROT(x, r) __funnelshift_l((x), (x), (r))
#else
#define TF_ROT(x, r) (((x) << (r)) | ((x) >> (32 - (r))))
#endif
#define TF_ROUND(r) { x0 += x1; x1 = TF_ROT(x1, r); x1 ^= x0; }
    TF_ROUND(13) TF_ROUND(15) TF_ROUND(26) TF_ROUND(6)
    x0 += k1; x1 += k2 + 1u;
    TF_ROUND(17) TF_ROUND(29) TF_ROUND(16) TF_ROUND(24)
    x0 += k2; x1 += k0 + 2u;
    TF_ROUND(13) TF_ROUND(15) TF_ROUND(26) TF_ROUND(6)
    x0 += k0; x1 += k1 + 3u;
    TF_ROUND(17) TF_ROUND(29) TF_ROUND(16) TF_ROUND(24)
    x0 += k1; x1 += k2 + 4u;
    TF_ROUND(13) TF_ROUND(15) TF_ROUND(26) TF_ROUND(6)
    x0 += k2; x1 += k0 + 5u;
#undef TF_ROUND
#undef TF_ROT
    o0 = x0; o1 = x1;
}

// Partitionable threefry bits: element i -> counter (0, i), output o0^o1.
__device__ __forceinline__ unsigned random_bits_partitionable(
    unsigned ka, unsigned kb, unsigned idx)
{
    unsigned o0, o1;
    threefry2x32(ka, kb, 0u, idx, o0, o1);
    return o0 ^ o1;
}

// Fast e = -log(u), rel err < ~1.2e-5 everywhere.
//  u >= 27/32: e = 2*atanh(z), z=(1-u)/(1+u) <= 0.0847 (1-u exact, Sterbenz);
//              p = 1 + y/3, trunc y^2/5 <= 1.04e-5 rel.
//  u <  27/32: e >= 0.1699, __logf abs err ~5e-7 -> rel <= 3e-6.
// u = f-1 without the tiny clamp: u==0 (P=2^-23) gives e=+inf -> r=0; every
// case where that element could matter lands in the exact fallback (thr==0
// or popc!=1), so argmax correctness is unaffected.
__device__ __forceinline__ float e_from_bits(unsigned bits)
{
    unsigned m = (bits >> 9) | 0x3f800000u;
    float u = __uint_as_float(m) - 1.0f;
    float lg = -__logf(u);
    float z = __fdividef(1.0f - u, 1.0f + u);
    float p = fmaf(z * z, 0.33333333333f, 1.0f);
    return (u >= 0.84375f) ? (2.0f * z * p) : lg;
}

// Exact uniform + gumbel (double-evaluated, correctly-rounded f32 chain).
__device__ __forceinline__ float uniform_exact(unsigned bits)
{
    const float tiny = 1.17549435082228750797e-38f;
    unsigned m = (bits >> 9) | 0x3f800000u;
    float u = __uint_as_float(m) - 1.0f;
    u = u + tiny;
    return fmaxf(tiny, u);
}
__device__ __forceinline__ float gumbel_exact(unsigned bits)
{
    float u = uniform_exact(bits);
    float l1 = (float)log((double)u);
    float l2 = (float)log((double)(-l1));
    return -l2;
}

// ---------------------------------------------------------------------------
// Cold path: bit-exact reference recomputation of one step's argmax.
// Lane owns elements d0=2*lane and d0+1. Warp-uniform entry.
// ---------------------------------------------------------------------------
__device__ __noinline__ int exact_argmax(
    float t0, float t1, bool v0, bool v1,
    unsigned ka, unsigned kb, unsigned ebase, int d0)
{
    const float LOG_EPS_EXACT = (float)log((double)EPSf);

    float m = fmaxf(t0, t1);
    #pragma unroll
    for (int o = 16; o; o >>= 1)
        m = fmaxf(m, __shfl_xor_sync(FULLMASK, m, o));
    const float tmax = (m > 0.0f) ? m : 1.0f;

    float ew0 = 0.0f, ew1 = 0.0f;
    if (v0) {
        float s = (float)((double)(t0 - tmax) / (double)0.1f);
        ew0 = (float)exp((double)s);
    }
    if (v1) {
        float s = (float)((double)(t1 - tmax) / (double)0.1f);
        ew1 = (float)exp((double)s);
    }
    double dsum = (double)ew0 + (double)ew1;
    #pragma unroll
    for (int o = 16; o; o >>= 1)
        dsum += __shfl_xor_sync(FULLMASK, dsum, o);
    dsum = __shfl_sync(FULLMASK, dsum, 0);
    const float denom = (float)dsum + EPSf;

    float sc0, sc1;
    {
        float g = gumbel_exact(random_bits_partitionable(ka, kb, ebase));
        float lp;
        if (v0) {
            float p = (float)((double)ew0 / (double)denom);
            lp = (float)log((double)(p + EPSf));
        } else lp = LOG_EPS_EXACT;
        sc0 = lp + g;
    }
    {
        float g = gumbel_exact(random_bits_partitionable(ka, kb, ebase + 1u));
        float lp;
        if (v1) {
            float p = (float)((double)ew1 / (double)denom);
            lp = (float)log((double)(p + EPSf));
        } else lp = LOG_EPS_EXACT;
        sc1 = lp + g;
    }

    float bs; int bix;
    if (sc1 > sc0) { bs = sc1; bix = d0 + 1; }
    else           { bs = sc0; bix = d0; }
    #pragma unroll
    for (int o = 16; o; o >>= 1) {
        float os = __shfl_xor_sync(FULLMASK, bs, o);
        int   oi = __shfl_xor_sync(FULLMASK, bix, o);
        if (os > bs || (os == bs && oi < bix)) { bs = os; bix = oi; }
    }
    return __shfl_sync(FULLMASK, bix, 0);
}

// ---------------------------------------------------------------------------
// Persistent warps, batched work fetch. Lane L owns elements d=2L, 2L+1.
// nvalid <= 32: rank-compact (d, w) into smem, ONE threefry per lane.
// nvalid >  32: direct two-threefry path (threefry load-independent).
// ---------------------------------------------------------------------------
__global__ void __launch_bounds__(128, 12)
walk_kernel(const int* __restrict__ src_nodes,
            const float* __restrict__ cur_times,
            const int* __restrict__ nb_ids,
            const float* __restrict__ nb_times,
            float* __restrict__ out,
            int B, StepKeys keys)
{
    __shared__ int2 s_dw[4][32];   // per-warp (element idx, w bits)

    const int lane = (int)(threadIdx.x & 31);
    const int wwarp = (int)(threadIdx.x >> 5);
    const unsigned nwalks = (unsigned)(B * W_WALKS);

    const size_t BWL = (size_t)nwalks * L_STEPS;
    float* const out_nodes = out;
    float* const out_times = out + BWL;
    float* const out_masks = out + 2 * BWL;

    const int d0 = lane << 1;
    unsigned ltmask;
    asm("mov.u32 %0, %%lanemask_lt;" : "=r"(ltmask));

    while (true) {
        // ---- fetch next batch of walks (warp-collective) ----
        unsigned batch = 0;
        if (lane == 0) batch = atomicAdd(&g_walk_ctr, WALK_BATCH);
        batch = __shfl_sync(FULLMASK, batch, 0);
        if (batch >= nwalks) return;
        const unsigned bend = min(batch + WALK_BATCH, nwalks);

        for (unsigned gw = batch; gw < bend; gw++) {
            const int gwarp = (int)gw;
            const int b = gwarp / W_WALKS;

            int   curr  = src_nodes[b];
            float ctime = cur_times[b];

            const size_t base = (size_t)gwarp * L_STEPS;
            const unsigned ebase64 = (unsigned)gwarp * DNB;

            if (lane == 0) {
                out_nodes[base] = (float)curr;
                out_times[base] = ctime;
                out_masks[base] = 1.0f;
            }

            int step = 1;
            #pragma unroll 1
            for (; step < L_STEPS; step++) {
                const unsigned rowo = (unsigned)curr * DNB;  // 32-bit safe
                const int2   ids = reinterpret_cast<const int2*>(nb_ids + rowo)[lane];
                const float2 ts  = reinterpret_cast<const float2*>(nb_times + rowo)[lane];
                const float t0 = ts.x, t1 = ts.y;

                const bool v0 = (t0 < ctime);
                const bool v1 = (t1 < ctime);
                const unsigned bL = __ballot_sync(FULLMASK, v0);
                const unsigned bH = __ballot_sync(FULLMASK, v1);
                const int nvalid = __popc(bL) + __popc(bH);

                if (nvalid == 0) break;   // walk dies; tail flushed below

                const unsigned ka = keys.a[step];
                const unsigned kb = keys.b[step];

                // weights, ctime-centered (warp-uniform frame factor ->
                // argmax-neutral; fp error within guard)
                const float ct14 = ctime * LOG2E10;
                float w0 = v0 ? exp2f(fmaf(t0, LOG2E10, -ct14)) : 0.0f;
                float w1 = v1 ? exp2f(fmaf(t1, LOG2E10, -ct14)) : 0.0f;

                // low-precision warp sum via fixed point + integer REDUX (S
                // only feeds the tiebreak constant c; 2% accuracy is ample).
                const unsigned wi = __float2uint_rn(w0 * FP_SCALE)
                                  + __float2uint_rn(w1 * FP_SCALE);
                const float ssum = (float)__reduce_add_sync(FULLMASK, wi) * FP_INV;
                const float c = EPSf * (ssum + EPSf);

                int bi = -1;

                if (nvalid <= 32) {
                    // ---- COMPACTED: rank-scatter (d, w) in element order;
                    // ONE threefry per lane.
                    const int rank0 = __popc(bL & ltmask) + __popc(bH & ltmask);
                    __syncwarp();   // WAR fence: prior winner read
                    if (v0) s_dw[wwarp][rank0] =
                        make_int2(d0, __float_as_int(w0));
                    if (v1) s_dw[wwarp][rank0 + (v0 ? 1 : 0)] =
                        make_int2(d0 + 1, __float_as_int(w1));
                    __syncwarp();

                    const int2  dw = s_dw[wwarp][(lane < nvalid) ? lane : 0];
                    const int   d  = dw.x;
                    const float wd = __int_as_float(dw.y);

                    float r = 0.0f;
                    if (lane < nvalid) {
                        const float e = e_from_bits(random_bits_partitionable(
                            ka, kb, ebase64 + (unsigned)d));
                        r = __fdividef(wd + c, e);
                    }

                    const unsigned bmax = __reduce_max_sync(
                        FULLMASK, __float_as_uint(r));
                    const float thr = __uint_as_float(bmax) * (1.0f - REL_GAP);

                    const unsigned bb = __ballot_sync(FULLMASK, r >= thr);
                    // unique in-band winner AND unscored masked elements
                    // provably below the band (r_masked <= c*1e7)
                    if (__popc(bb) == 1 && thr > c * MASKED_C_MULT)
                        bi = s_dw[wwarp][__ffs(bb) - 1].x;
                } else {
                    // ---- FULL: both elements per lane; threefry independent
                    // of the gathers (overlaps load latency). Masked elements
                    // get r = c/e, exactly the reference surrogate, for free.
                    const float e0 = e_from_bits(random_bits_partitionable(
                        ka, kb, ebase64 + (unsigned)d0));
                    const float e1 = e_from_bits(random_bits_partitionable(
                        ka, kb, ebase64 + (unsigned)d0 + 1u));
                    const float r0 = __fdividef(w0 + c, e0);
                    const float r1 = __fdividef(w1 + c, e1);

                    const unsigned bmax = __reduce_max_sync(
                        FULLMASK, __float_as_uint(fmaxf(r0, r1)));
                    const float thr = __uint_as_float(bmax) * (1.0f - REL_GAP);

                    const unsigned bb0 = __ballot_sync(FULLMASK, r0 >= thr);
                    const unsigned bb1 = __ballot_sync(FULLMASK, r1 >= thr);
                    if (__popc(bb0) + __popc(bb1) == 1)
                        bi = bb0 ? ((__ffs(bb0) - 1) << 1)
                                 : (((__ffs(bb1) - 1) << 1) | 1);
                }

                if (bi < 0)  // warp-uniform: guard failed -> bit-exact path
                    bi = exact_argmax(t0, t1, v0, v1, ka, kb,
                                      ebase64 + (unsigned)d0, d0);

                // fetch chosen neighbor from its owner lane (bi warp-uniform)
                const int   slot = (bi & 1);
                const int   nid = __shfl_sync(FULLMASK, slot ? ids.y : ids.x, bi >> 1);
                const float nt  = __shfl_sync(FULLMASK, slot ? t1    : t0,   bi >> 1);

                curr = nid;
                ctime = nt;

                if (lane == 0) {
                    out_nodes[base + step] = (float)curr;
                    out_times[base + step] = ctime;
                    out_masks[base + step] = 1.0f;
                }
            }

            // dead-walk tail: sticky values, mask 0
            if (lane == 0) {
                for (int s2 = step; s2 < L_STEPS; s2++) {
                    out_nodes[base + s2] = (float)curr;
                    out_times[base + s2] = ctime;
                    out_masks[base + s2] = 0.0f;
                }
            }
        }
    }
}

// ---------------------------------------------------------------------------
extern "C" void kernel_launch(void* const* d_in, const int* in_sizes, int n_in,
                              void* d_out, int out_size)
{
    const int*   src = (const int*)d_in[0];
    const float* ct  = (const float*)d_in[1];
    const int*   nid = (const int*)d_in[2];
    const float* nt  = (const float*)d_in[3];
    const int B = in_sizes[0];

    // fold_in(key(42), step) = threefry2x32((0,42), (0,step))
    StepKeys keys;
    for (int s = 0; s < L_STEPS; s++) { keys.a[s] = 0; keys.b[s] = 0; }
    for (int s = 1; s < L_STEPS; s++) {
        unsigned o0, o1;
        threefry2x32(0u, 42u, 0u, (unsigned)s, o0, o1);
        keys.a[s] = o0; keys.b[s] = o1;
    }

    // Persistent grid: 12 blocks/SM x 152 SMs. Extra blocks are harmless
    // (they exit when the queue is empty).
    reset_ctr_kernel<<<1, 1>>>();
    walk_kernel<<<1824, 128>>>(src, ct, nid, nt, (float*)d_out, B, keys);
}

// round 15
// speedup vs baseline: 1.0905x; 1.0905x over previous
#include <cuda_runtime.h>
#include <cstdint>
#include <math.h>

// Problem constants: W=num_walks=10, L=walk_length=10, D=64 neighbors.
#define W_WALKS 10
#define L_STEPS 10
#define DNB 64
#define FULLMASK 0xFFFFFFFFu

#define EPSf 1e-10f
#define REL_GAP 1e-4f          // relative guard band (fast errors ~3e-5)
// masked surrogate bound: r_masked = c/e <= c*8.39e6; widened to absorb the
// ~2% fixed-point error in S.
#define MASKED_C_MULT 1.0e7f
#define LOG2E10 14.4269504089f // 10 * log2(e)
#define FP_SCALE 33554432.0f   // 2^25
#define FP_INV   2.9802322387695312e-8f // 2^-25

struct StepKeys {
    unsigned a[L_STEPS];
    unsigned b[L_STEPS];
};

// Persistent-warp work queue.
__device__ unsigned g_walk_ctr;

__global__ void reset_ctr_kernel() { g_walk_ctr = 0u; }

// ---------------------------------------------------------------------------
// Threefry-2x32 (20 rounds), matching jax._src.prng.threefry2x32 exactly.
// ---------------------------------------------------------------------------
__host__ __device__ __forceinline__ void threefry2x32(
    unsigned k0, unsigned k1, unsigned x0, unsigned x1,
    unsigned& o0, unsigned& o1)
{
    unsigned k2 = k0 ^ k1 ^ 0x1BD11BDAu;
    x0 += k0; x1 += k1;
#if defined(__CUDA_ARCH__)
#define TF_ROT(x, r) __funnelshift_l((x), (x), (r))
#else
#define TF_ROT(x, r) (((x) << (r)) | ((x) >> (32 - (r))))
#endif
#define TF_ROUND(r) { x0 += x1; x1 = TF_ROT(x1, r); x1 ^= x0; }
    TF_ROUND(13) TF_ROUND(15) TF_ROUND(26) TF_ROUND(6)
    x0 += k1; x1 += k2 + 1u;
    TF_ROUND(17) TF_ROUND(29) TF_ROUND(16) TF_ROUND(24)
    x0 += k2; x1 += k0 + 2u;
    TF_ROUND(13) TF_ROUND(15) TF_ROUND(26) TF_ROUND(6)
    x0 += k0; x1 += k1 + 3u;
    TF_ROUND(17) TF_ROUND(29) TF_ROUND(16) TF_ROUND(24)
    x0 += k1; x1 += k2 + 4u;
    TF_ROUND(13) TF_ROUND(15) TF_ROUND(26) TF_ROUND(6)
    x0 += k2; x1 += k0 + 5u;
#undef TF_ROUND
#undef TF_ROT
    o0 = x0; o1 = x1;
}

// Partitionable threefry bits: element i -> counter (0, i), output o0^o1.
__device__ __forceinline__ unsigned random_bits_partitionable(
    unsigned ka, unsigned kb, unsigned idx)
{
    unsigned o0, o1;
    threefry2x32(ka, kb, 0u, idx, o0, o1);
    return o0 ^ o1;
}

// Fast e = -log(u), rel err < ~1.2e-5 everywhere.
//  u >= 27/32: e = 2*atanh(z), z=(1-u)/(1+u) <= 0.0847 (1-u exact, Sterbenz);
//              p = 1 + y/3, trunc y^2/5 <= 1.04e-5 rel.
//  u <  27/32: e >= 0.1699, __logf abs err ~5e-7 -> rel <= 3e-6.
// u = f-1 without the tiny clamp: u==0 (P=2^-23) gives e=+inf -> r=0; every
// case where that element could matter lands in the exact fallback (thr==0
// or popc!=1), so argmax correctness is unaffected.
__device__ __forceinline__ float e_from_bits(unsigned bits)
{
    unsigned m = (bits >> 9) | 0x3f800000u;
    float u = __uint_as_float(m) - 1.0f;
    float lg = -__logf(u);
    float z = __fdividef(1.0f - u, 1.0f + u);
    float p = fmaf(z * z, 0.33333333333f, 1.0f);
    return (u >= 0.84375f) ? (2.0f * z * p) : lg;
}

// Exact uniform + gumbel (double-evaluated, correctly-rounded f32 chain).
__device__ __forceinline__ float uniform_exact(unsigned bits)
{
    const float tiny = 1.17549435082228750797e-38f;
    unsigned m = (bits >> 9) | 0x3f800000u;
    float u = __uint_as_float(m) - 1.0f;
    u = u + tiny;
    return fmaxf(tiny, u);
}
__device__ __forceinline__ float gumbel_exact(unsigned bits)
{
    float u = uniform_exact(bits);
    float l1 = (float)log((double)u);
    float l2 = (float)log((double)(-l1));
    return -l2;
}

// ---------------------------------------------------------------------------
// Cold path: bit-exact reference recomputation of one step's argmax.
// Lane owns elements d0=2*lane and d0+1. Warp-uniform entry.
// ---------------------------------------------------------------------------
__device__ __noinline__ int exact_argmax(
    float t0, float t1, bool v0, bool v1,
    unsigned ka, unsigned kb, unsigned ebase, int d0)
{
    const float LOG_EPS_EXACT = (float)log((double)EPSf);

    float m = fmaxf(t0, t1);
    #pragma unroll
    for (int o = 16; o; o >>= 1)
        m = fmaxf(m, __shfl_xor_sync(FULLMASK, m, o));
    const float tmax = (m > 0.0f) ? m : 1.0f;

    float ew0 = 0.0f, ew1 = 0.0f;
    if (v0) {
        float s = (float)((double)(t0 - tmax) / (double)0.1f);
        ew0 = (float)exp((double)s);
    }
    if (v1) {
        float s = (float)((double)(t1 - tmax) / (double)0.1f);
        ew1 = (float)exp((double)s);
    }
    double dsum = (double)ew0 + (double)ew1;
    #pragma unroll
    for (int o = 16; o; o >>= 1)
        dsum += __shfl_xor_sync(FULLMASK, dsum, o);
    dsum = __shfl_sync(FULLMASK, dsum, 0);
    const float denom = (float)dsum + EPSf;

    float sc0, sc1;
    {
        float g = gumbel_exact(random_bits_partitionable(ka, kb, ebase));
        float lp;
        if (v0) {
            float p = (float)((double)ew0 / (double)denom);
            lp = (float)log((double)(p + EPSf));
        } else lp = LOG_EPS_EXACT;
        sc0 = lp + g;
    }
    {
        float g = gumbel_exact(random_bits_partitionable(ka, kb, ebase + 1u));
        float lp;
        if (v1) {
            float p = (float)((double)ew1 / (double)denom);
            lp = (float)log((double)(p + EPSf));
        } else lp = LOG_EPS_EXACT;
        sc1 = lp + g;
    }

    float bs; int bix;
    if (sc1 > sc0) { bs = sc1; bix = d0 + 1; }
    else           { bs = sc0; bix = d0; }
    #pragma unroll
    for (int o = 16; o; o >>= 1) {
        float os = __shfl_xor_sync(FULLMASK, bs, o);
        int   oi = __shfl_xor_sync(FULLMASK, bix, o);
        if (os > bs || (os == bs && oi < bix)) { bs = os; bix = oi; }
    }
    return __shfl_sync(FULLMASK, bix, 0);
}

// ---------------------------------------------------------------------------
// Persistent warps, per-walk dynamic fetch (fine granularity = the load
// balancer; batching regressed in R14). Lane L owns elements d=2L, 2L+1.
// nvalid <= 32: rank-compact (d, w) into smem, ONE threefry per lane.
// nvalid >  32: direct two-threefry path (threefry load-independent).
// ---------------------------------------------------------------------------
__global__ void __launch_bounds__(128, 12)
walk_kernel(const int* __restrict__ src_nodes,
            const float* __restrict__ cur_times,
            const int* __restrict__ nb_ids,
            const float* __restrict__ nb_times,
            float* __restrict__ out,
            int B, StepKeys keys)
{
    __shared__ int2 s_dw[4][32];   // per-warp (element idx, w bits)

    const int lane = (int)(threadIdx.x & 31);
    const int wwarp = (int)(threadIdx.x >> 5);
    const unsigned nwalks = (unsigned)(B * W_WALKS);

    const size_t BWL = (size_t)nwalks * L_STEPS;
    float* const out_nodes = out;
    float* const out_times = out + BWL;
    float* const out_masks = out + 2 * BWL;

    const int d0 = lane << 1;
    unsigned ltmask;
    asm("mov.u32 %0, %%lanemask_lt;" : "=r"(ltmask));

    while (true) {
        // ---- fetch next walk (warp-collective) ----
        unsigned gwarp_u = 0;
        if (lane == 0) gwarp_u = atomicAdd(&g_walk_ctr, 1u);
        gwarp_u = __shfl_sync(FULLMASK, gwarp_u, 0);
        if (gwarp_u >= nwalks) return;
        const int gwarp = (int)gwarp_u;
        const int b = gwarp / W_WALKS;

        int   curr  = src_nodes[b];
        float ctime = cur_times[b];

        const size_t base = (size_t)gwarp * L_STEPS;
        const unsigned ebase64 = (unsigned)gwarp * DNB;

        if (lane == 0) {
            out_nodes[base] = (float)curr;
            out_times[base] = ctime;
            out_masks[base] = 1.0f;
        }

        int step = 1;
        #pragma unroll 1
        for (; step < L_STEPS; step++) {
            const unsigned rowo = (unsigned)curr * DNB;  // 32-bit safe
            const int2   ids = reinterpret_cast<const int2*>(nb_ids + rowo)[lane];
            const float2 ts  = reinterpret_cast<const float2*>(nb_times + rowo)[lane];
            const float t0 = ts.x, t1 = ts.y;

            const bool v0 = (t0 < ctime);
            const bool v1 = (t1 < ctime);
            const unsigned bL = __ballot_sync(FULLMASK, v0);
            const unsigned bH = __ballot_sync(FULLMASK, v1);
            const int nvalid = __popc(bL) + __popc(bH);

            if (nvalid == 0) break;   // walk dies; tail flushed below

            const unsigned ka = keys.a[step];
            const unsigned kb = keys.b[step];

            // weights, ctime-centered (warp-uniform frame factor -> argmax-
            // neutral; fp error within guard)
            const float ct14 = ctime * LOG2E10;
            float w0 = v0 ? exp2f(fmaf(t0, LOG2E10, -ct14)) : 0.0f;
            float w1 = v1 ? exp2f(fmaf(t1, LOG2E10, -ct14)) : 0.0f;

            // low-precision warp sum via fixed point + integer REDUX (S is
            // only used for the tiebreak constant c; 2% accuracy is ample).
            const unsigned wi = __float2uint_rn(w0 * FP_SCALE)
                              + __float2uint_rn(w1 * FP_SCALE);
            const float ssum = (float)__reduce_add_sync(FULLMASK, wi) * FP_INV;
            const float c = EPSf * (ssum + EPSf);

            int bi = -1;

            if (nvalid <= 32) {
                // ---- COMPACTED: rank-scatter (d, w) in element order; ONE
                // threefry per lane.
                const int rank0 = __popc(bL & ltmask) + __popc(bH & ltmask);
                __syncwarp();   // WAR: prior iteration's winner read
                if (v0) s_dw[wwarp][rank0] =
                    make_int2(d0, __float_as_int(w0));
                if (v1) s_dw[wwarp][rank0 + (v0 ? 1 : 0)] =
                    make_int2(d0 + 1, __float_as_int(w1));
                __syncwarp();

                const int2  dw = s_dw[wwarp][(lane < nvalid) ? lane : 0];
                const int   d  = dw.x;
                const float wd = __int_as_float(dw.y);

                float r = 0.0f;
                if (lane < nvalid) {
                    const float e = e_from_bits(random_bits_partitionable(
                        ka, kb, ebase64 + (unsigned)d));
                    r = __fdividef(wd + c, e);
                }

                const unsigned bmax = __reduce_max_sync(
                    FULLMASK, __float_as_uint(r));
                const float thr = __uint_as_float(bmax) * (1.0f - REL_GAP);

                const unsigned bb = __ballot_sync(FULLMASK, r >= thr);
                // unique in-band winner AND unscored masked elements provably
                // below the band (r_masked <= c*1e7 incl. S error margin)
                if (__popc(bb) == 1 && thr > c * MASKED_C_MULT)
                    bi = s_dw[wwarp][__ffs(bb) - 1].x;
            } else {
                // ---- FULL: both elements per lane; threefry independent of
                // the gathers (overlaps load latency). Masked elements get
                // r = c/e, exactly the reference surrogate, for free.
                const float e0 = e_from_bits(random_bits_partitionable(
                    ka, kb, ebase64 + (unsigned)d0));
                const float e1 = e_from_bits(random_bits_partitionable(
                    ka, kb, ebase64 + (unsigned)d0 + 1u));
                const float r0 = __fdividef(w0 + c, e0);
                const float r1 = __fdividef(w1 + c, e1);

                const unsigned bmax = __reduce_max_sync(
                    FULLMASK, __float_as_uint(fmaxf(r0, r1)));
                const float thr = __uint_as_float(bmax) * (1.0f - REL_GAP);

                const unsigned bb0 = __ballot_sync(FULLMASK, r0 >= thr);
                const unsigned bb1 = __ballot_sync(FULLMASK, r1 >= thr);
                if (__popc(bb0) + __popc(bb1) == 1)
                    bi = bb0 ? ((__ffs(bb0) - 1) << 1)
                             : (((__ffs(bb1) - 1) << 1) | 1);
            }

            if (bi < 0)  // warp-uniform: guard failed -> bit-exact path
                bi = exact_argmax(t0, t1, v0, v1, ka, kb,
                                  ebase64 + (unsigned)d0, d0);

            // fetch chosen neighbor from its owner lane (bi warp-uniform)
            const int   slot = (bi & 1);
            const int   nid = __shfl_sync(FULLMASK, slot ? ids.y : ids.x, bi >> 1);
            const float nt  = __shfl_sync(FULLMASK, slot ? t1    : t0,   bi >> 1);

            curr = nid;
            ctime = nt;

            if (lane == 0) {
                out_nodes[base + step] = (float)curr;
                out_times[base + step] = ctime;
                out_masks[base + step] = 1.0f;
            }
        }

        // dead-walk tail: sticky values, mask 0
        if (lane == 0) {
            for (int s2 = step; s2 < L_STEPS; s2++) {
                out_nodes[base + s2] = (float)curr;
                out_times[base + s2] = ctime;
                out_masks[base + s2] = 0.0f;
            }
        }
    }
}

// ---------------------------------------------------------------------------
extern "C" void kernel_launch(void* const* d_in, const int* in_sizes, int n_in,
                              void* d_out, int out_size)
{
    const int*   src = (const int*)d_in[0];
    const float* ct  = (const float*)d_in[1];
    const int*   nid = (const int*)d_in[2];
    const float* nt  = (const float*)d_in[3];
    const int B = in_sizes[0];

    // fold_in(key(42), step) = threefry2x32((0,42), (0,step))
    StepKeys keys;
    for (int s = 0; s < L_STEPS; s++) { keys.a[s] = 0; keys.b[s] = 0; }
    for (int s = 1; s < L_STEPS; s++) {
        unsigned o0, o1;
        threefry2x32(0u, 42u, 0u, (unsigned)s, o0, o1);
        keys.a[s] = o0; keys.b[s] = o1;
    }

    // Persistent grid: 12 blocks/SM x 152 SMs. Extra blocks are harmless
    // (they exit when the queue is empty).
    reset_ctr_kernel<<<1, 1>>>();
    walk_kernel<<<1824, 128>>>(src, ct, nid, nt, (float*)d_out, B, keys);
}

// round 16
// speedup vs baseline: 1.1202x; 1.0272x over previous
#include <cuda_runtime.h>
#include <cstdint>
#include <math.h>

// Problem constants: W=num_walks=10, L=walk_length=10, D=64 neighbors.
#define W_WALKS 10
#define L_STEPS 10
#define DNB 64
#define FULLMASK 0xFFFFFFFFu

#define EPSf 1e-10f
#define REL_GAP 1e-4f          // relative guard band (fast errors ~3e-5)
// masked surrogate bound: r_masked = c/e <= c*8.39e6; widened to absorb the
// ~2% fixed-point error in S.
#define MASKED_C_MULT 1.0e7f
#define LOG2E10 14.4269504089f // 10 * log2(e)
#define FP_SCALE 33554432.0f   // 2^25
#define FP_INV   2.9802322387695312e-8f // 2^-25

struct StepKeys {
    unsigned a[L_STEPS];
    unsigned b[L_STEPS];
};

// Persistent-warp work queue.
__device__ unsigned g_walk_ctr;

__global__ void reset_ctr_kernel() { g_walk_ctr = 0u; }

// ---------------------------------------------------------------------------
// Threefry-2x32 (20 rounds), matching jax._src.prng.threefry2x32 exactly.
// ---------------------------------------------------------------------------
__host__ __device__ __forceinline__ void threefry2x32(
    unsigned k0, unsigned k1, unsigned x0, unsigned x1,
    unsigned& o0, unsigned& o1)
{
    unsigned k2 = k0 ^ k1 ^ 0x1BD11BDAu;
    x0 += k0; x1 += k1;
#if defined(__CUDA_ARCH__)
#define TF_ROT(x, r) __funnelshift_l((x), (x), (r))
#else
#define TF_ROT(x, r) (((x) << (r)) | ((x) >> (32 - (r))))
#endif
#define TF_ROUND(r) { x0 += x1; x1 = TF_ROT(x1, r); x1 ^= x0; }
    TF_ROUND(13) TF_ROUND(15) TF_ROUND(26) TF_ROUND(6)
    x0 += k1; x1 += k2 + 1u;
    TF_ROUND(17) TF_ROUND(29) TF_ROUND(16) TF_ROUND(24)
    x0 += k2; x1 += k0 + 2u;
    TF_ROUND(13) TF_ROUND(15) TF_ROUND(26) TF_ROUND(6)
    x0 += k0; x1 += k1 + 3u;
    TF_ROUND(17) TF_ROUND(29) TF_ROUND(16) TF_ROUND(24)
    x0 += k1; x1 += k2 + 4u;
    TF_ROUND(13) TF_ROUND(15) TF_ROUND(26) TF_ROUND(6)
    x0 += k2; x1 += k0 + 5u;
#undef TF_ROUND
#undef TF_ROT
    o0 = x0; o1 = x1;
}

// Partitionable threefry bits: element i -> counter (0, i), output o0^o1.
__device__ __forceinline__ unsigned random_bits_partitionable(
    unsigned ka, unsigned kb, unsigned idx)
{
    unsigned o0, o1;
    threefry2x32(ka, kb, 0u, idx, o0, o1);
    return o0 ^ o1;
}

// Fast e = -log(u), rel err < ~1.2e-5 everywhere.
//  u >= 27/32: e = 2*atanh(z), z=(1-u)/(1+u) <= 0.0847 (1-u exact, Sterbenz);
//              p = 1 + y/3, trunc y^2/5 <= 1.04e-5 rel.
//  u <  27/32: e >= 0.1699, __logf abs err ~5e-7 -> rel <= 3e-6.
// u = f-1 without the tiny clamp: u==0 (P=2^-23) gives e=+inf -> r=0; every
// case where that element could matter lands in the exact fallback (thr==0
// or popc!=1), so argmax correctness is unaffected.
__device__ __forceinline__ float e_from_bits(unsigned bits)
{
    unsigned m = (bits >> 9) | 0x3f800000u;
    float u = __uint_as_float(m) - 1.0f;
    float lg = -__logf(u);
    float z = __fdividef(1.0f - u, 1.0f + u);
    float p = fmaf(z * z, 0.33333333333f, 1.0f);
    return (u >= 0.84375f) ? (2.0f * z * p) : lg;
}

// Exact uniform + gumbel (double-evaluated, correctly-rounded f32 chain).
__device__ __forceinline__ float uniform_exact(unsigned bits)
{
    const float tiny = 1.17549435082228750797e-38f;
    unsigned m = (bits >> 9) | 0x3f800000u;
    float u = __uint_as_float(m) - 1.0f;
    u = u + tiny;
    return fmaxf(tiny, u);
}
__device__ __forceinline__ float gumbel_exact(unsigned bits)
{
    float u = uniform_exact(bits);
    float l1 = (float)log((double)u);
    float l2 = (float)log((double)(-l1));
    return -l2;
}

// ---------------------------------------------------------------------------
// Cold path: bit-exact reference recomputation of one step's argmax.
// Lane owns elements d0=2*lane and d0+1. Warp-uniform entry.
// ---------------------------------------------------------------------------
__device__ __noinline__ int exact_argmax(
    float t0, float t1, bool v0, bool v1,
    unsigned ka, unsigned kb, unsigned ebase, int d0)
{
    const float LOG_EPS_EXACT = (float)log((double)EPSf);

    float m = fmaxf(t0, t1);
    #pragma unroll
    for (int o = 16; o; o >>= 1)
        m = fmaxf(m, __shfl_xor_sync(FULLMASK, m, o));
    const float tmax = (m > 0.0f) ? m : 1.0f;

    float ew0 = 0.0f, ew1 = 0.0f;
    if (v0) {
        float s = (float)((double)(t0 - tmax) / (double)0.1f);
        ew0 = (float)exp((double)s);
    }
    if (v1) {
        float s = (float)((double)(t1 - tmax) / (double)0.1f);
        ew1 = (float)exp((double)s);
    }
    double dsum = (double)ew0 + (double)ew1;
    #pragma unroll
    for (int o = 16; o; o >>= 1)
        dsum += __shfl_xor_sync(FULLMASK, dsum, o);
    dsum = __shfl_sync(FULLMASK, dsum, 0);
    const float denom = (float)dsum + EPSf;

    float sc0, sc1;
    {
        float g = gumbel_exact(random_bits_partitionable(ka, kb, ebase));
        float lp;
        if (v0) {
            float p = (float)((double)ew0 / (double)denom);
            lp = (float)log((double)(p + EPSf));
        } else lp = LOG_EPS_EXACT;
        sc0 = lp + g;
    }
    {
        float g = gumbel_exact(random_bits_partitionable(ka, kb, ebase + 1u));
        float lp;
        if (v1) {
            float p = (float)((double)ew1 / (double)denom);
            lp = (float)log((double)(p + EPSf));
        } else lp = LOG_EPS_EXACT;
        sc1 = lp + g;
    }

    float bs; int bix;
    if (sc1 > sc0) { bs = sc1; bix = d0 + 1; }
    else           { bs = sc0; bix = d0; }
    #pragma unroll
    for (int o = 16; o; o >>= 1) {
        float os = __shfl_xor_sync(FULLMASK, bs, o);
        int   oi = __shfl_xor_sync(FULLMASK, bix, o);
        if (os > bs || (os == bs && oi < bix)) { bs = os; bix = oi; }
    }
    return __shfl_sync(FULLMASK, bix, 0);
}

// ---------------------------------------------------------------------------
// Persistent warps, per-walk dynamic fetch (fine granularity = the load
// balancer). Lane L owns elements d=2L, 2L+1 (vector loads).
// nvalid <= 32: rank-compact (threefry_idx, w, t, id) int4 records into smem;
//               ONE threefry per lane; the winner's (id, t) come straight
//               from one LDS.128 — no shfl on the critical chain.
// nvalid >  32: direct two-threefry path (threefry load-independent).
// ---------------------------------------------------------------------------
__global__ void __launch_bounds__(128, 12)
walk_kernel(const int* __restrict__ src_nodes,
            const float* __restrict__ cur_times,
            const int* __restrict__ nb_ids,
            const float* __restrict__ nb_times,
            float* __restrict__ out,
            int B, StepKeys keys)
{
    __shared__ int4 s_q[4][32];   // per-warp (threefry idx, w, t, id)

    const int lane = (int)(threadIdx.x & 31);
    const int wwarp = (int)(threadIdx.x >> 5);
    const unsigned nwalks = (unsigned)(B * W_WALKS);

    const size_t BWL = (size_t)nwalks * L_STEPS;
    float* const out_nodes = out;
    float* const out_times = out + BWL;
    float* const out_masks = out + 2 * BWL;

    const int d0 = lane << 1;
    unsigned ltmask;
    asm("mov.u32 %0, %%lanemask_lt;" : "=r"(ltmask));

    while (true) {
        // ---- fetch next walk (warp-collective) ----
        unsigned gwarp_u = 0;
        if (lane == 0) gwarp_u = atomicAdd(&g_walk_ctr, 1u);
        gwarp_u = __shfl_sync(FULLMASK, gwarp_u, 0);
        if (gwarp_u >= nwalks) return;
        const int gwarp = (int)gwarp_u;
        const int b = gwarp / W_WALKS;

        int   curr  = src_nodes[b];
        float ctime = cur_times[b];

        const size_t base = (size_t)gwarp * L_STEPS;
        const unsigned ebase64 = (unsigned)gwarp * DNB;
        const unsigned elane0 = ebase64 + (unsigned)d0;   // this lane's idx

        if (lane == 0) {
            out_nodes[base] = (float)curr;
            out_times[base] = ctime;
            out_masks[base] = 1.0f;
        }

        int step = 1;
        #pragma unroll 1
        for (; step < L_STEPS; step++) {
            const unsigned rowo = (unsigned)curr * DNB;  // 32-bit safe
            const int2   ids = reinterpret_cast<const int2*>(nb_ids + rowo)[lane];
            const float2 ts  = reinterpret_cast<const float2*>(nb_times + rowo)[lane];
            const float t0 = ts.x, t1 = ts.y;

            const bool v0 = (t0 < ctime);
            const bool v1 = (t1 < ctime);
            const unsigned bL = __ballot_sync(FULLMASK, v0);
            const unsigned bH = __ballot_sync(FULLMASK, v1);
            const int nvalid = __popc(bL) + __popc(bH);

            if (nvalid == 0) break;   // walk dies; tail flushed below

            const unsigned ka = keys.a[step];
            const unsigned kb = keys.b[step];

            // weights, ctime-centered (warp-uniform frame factor -> argmax-
            // neutral; fp error within guard)
            const float ct14 = ctime * LOG2E10;
            float w0 = v0 ? exp2f(fmaf(t0, LOG2E10, -ct14)) : 0.0f;
            float w1 = v1 ? exp2f(fmaf(t1, LOG2E10, -ct14)) : 0.0f;

            // low-precision warp sum via fixed point + integer REDUX (S is
            // only used for the tiebreak constant c; 2% accuracy is ample).
            const unsigned wi = __float2uint_rn(w0 * FP_SCALE)
                              + __float2uint_rn(w1 * FP_SCALE);
            const float ssum = (float)__reduce_add_sync(FULLMASK, wi) * FP_INV;
            const float c = EPSf * (ssum + EPSf);

            bool resolved = false;
            int bi = -1;   // only meaningful for full/fallback paths

            if (nvalid <= 32) {
                // ---- COMPACTED: rank-scatter full records in element
                // order; ONE threefry per lane; winner via one LDS.128.
                const int rank0 = __popc(bL & ltmask) + __popc(bH & ltmask);
                __syncwarp();   // WAR: prior iteration's winner read
                if (v0) s_q[wwarp][rank0] = make_int4(
                    (int)elane0, __float_as_int(w0),
                    __float_as_int(t0), ids.x);
                if (v1) s_q[wwarp][rank0 + (v0 ? 1 : 0)] = make_int4(
                    (int)(elane0 + 1u), __float_as_int(w1),
                    __float_as_int(t1), ids.y);
                __syncwarp();

                const int4  q  = s_q[wwarp][(lane < nvalid) ? lane : 0];
                const float wd = __int_as_float(q.y);

                float r = 0.0f;
                if (lane < nvalid) {
                    const float e = e_from_bits(random_bits_partitionable(
                        ka, kb, (unsigned)q.x));
                    r = __fdividef(wd + c, e);
                }

                const unsigned bmax = __reduce_max_sync(
                    FULLMASK, __float_as_uint(r));
                const float thr = __uint_as_float(bmax) * (1.0f - REL_GAP);

                const unsigned bb = __ballot_sync(FULLMASK, r >= thr);
                // unique in-band winner AND unscored masked elements provably
                // below the band (r_masked <= c*1e7 incl. S error margin)
                if (__popc(bb) == 1 && thr > c * MASKED_C_MULT) {
                    const int4 qw = s_q[wwarp][__ffs(bb) - 1];
                    curr  = qw.w;                      // id
                    ctime = __int_as_float(qw.z);      // t
                    resolved = true;
                }
            } else {
                // ---- FULL: both elements per lane; threefry independent of
                // the gathers (overlaps load latency). Masked elements get
                // r = c/e, exactly the reference surrogate, for free.
                const float e0 = e_from_bits(random_bits_partitionable(
                    ka, kb, elane0));
                const float e1 = e_from_bits(random_bits_partitionable(
                    ka, kb, elane0 + 1u));
                const float r0 = __fdividef(w0 + c, e0);
                const float r1 = __fdividef(w1 + c, e1);

                const unsigned bmax = __reduce_max_sync(
                    FULLMASK, __float_as_uint(fmaxf(r0, r1)));
                const float thr = __uint_as_float(bmax) * (1.0f - REL_GAP);

                const unsigned bb0 = __ballot_sync(FULLMASK, r0 >= thr);
                const unsigned bb1 = __ballot_sync(FULLMASK, r1 >= thr);
                if (__popc(bb0) + __popc(bb1) == 1)
                    bi = bb0 ? ((__ffs(bb0) - 1) << 1)
                             : (((__ffs(bb1) - 1) << 1) | 1);
            }

            if (!resolved) {
                if (bi < 0)  // warp-uniform: guard failed -> bit-exact path
                    bi = exact_argmax(t0, t1, v0, v1, ka, kb, elane0, d0);

                // fetch chosen neighbor from its owner lane (bi uniform)
                const int slot = (bi & 1);
                curr  = __shfl_sync(FULLMASK, slot ? ids.y : ids.x, bi >> 1);
                ctime = __shfl_sync(FULLMASK, slot ? t1    : t0,   bi >> 1);
            }

            if (lane == 0) {
                out_nodes[base + step] = (float)curr;
                out_times[base + step] = ctime;
                out_masks[base + step] = 1.0f;
            }
        }

        // dead-walk tail: sticky values, mask 0
        if (lane == 0) {
            for (int s2 = step; s2 < L_STEPS; s2++) {
                out_nodes[base + s2] = (float)curr;
                out_times[base + s2] = ctime;
                out_masks[base + s2] = 0.0f;
            }
        }
    }
}

// ---------------------------------------------------------------------------
extern "C" void kernel_launch(void* const* d_in, const int* in_sizes, int n_in,
                              void* d_out, int out_size)
{
    const int*   src = (const int*)d_in[0];
    const float* ct  = (const float*)d_in[1];
    const int*   nid = (const int*)d_in[2];
    const float* nt  = (const float*)d_in[3];
    const int B = in_sizes[0];

    // fold_in(key(42), step) = threefry2x32((0,42), (0,step))
    StepKeys keys;
    for (int s = 0; s < L_STEPS; s++) { keys.a[s] = 0; keys.b[s] = 0; }
    for (int s = 1; s < L_STEPS; s++) {
        unsigned o0, o1;
        threefry2x32(0u, 42u, 0u, (unsigned)s, o0, o1);
        keys.a[s] = o0; keys.b[s] = o1;
    }

    // Persistent grid: 12 blocks/SM x 152 SMs. Extra blocks are harmless
    // (they exit when the queue is empty).
    reset_ctr_kernel<<<1, 1>>>();
    walk_kernel<<<1824, 128>>>(src, ct, nid, nt, (float*)d_out, B, keys);
}

// round 17
// speedup vs baseline: 1.1267x; 1.0058x over previous
#include <cuda_runtime.h>
#include <cstdint>
#include <math.h>

// Problem constants: W=num_walks=10, L=walk_length=10, D=64 neighbors.
#define W_WALKS 10
#define L_STEPS 10
#define DNB 64
#define FULLMASK 0xFFFFFFFFu

#define EPSf 1e-10f
#define REL_GAP 1e-4f          // relative guard band (fast errors ~3e-5)
// masked surrogate bound: r_masked = c/e <= c*8.39e6; widened to absorb the
// ~2% fixed-point error in S.
#define MASKED_C_MULT 1.0e7f
#define LOG2E10 14.4269504089f // 10 * log2(e)
#define FP_SCALE 33554432.0f   // 2^25
#define FP_INV   2.9802322387695312e-8f // 2^-25

struct StepKeys {
    unsigned a[L_STEPS];
    unsigned b[L_STEPS];
};

// Persistent-warp work queue.
__device__ unsigned g_walk_ctr;

__global__ void reset_ctr_kernel() { g_walk_ctr = 0u; }

// ---------------------------------------------------------------------------
// Threefry-2x32 (20 rounds), matching jax._src.prng.threefry2x32 exactly.
// ---------------------------------------------------------------------------
__host__ __device__ __forceinline__ void threefry2x32(
    unsigned k0, unsigned k1, unsigned x0, unsigned x1,
    unsigned& o0, unsigned& o1)
{
    unsigned k2 = k0 ^ k1 ^ 0x1BD11BDAu;
    x0 += k0; x1 += k1;
#if defined(__CUDA_ARCH__)
#define TF_ROT(x, r) __funnelshift_l((x), (x), (r))
#else
#define TF_ROT(x, r) (((x) << (r)) | ((x) >> (32 - (r))))
#endif
#define TF_ROUND(r) { x0 += x1; x1 = TF_ROT(x1, r); x1 ^= x0; }
    TF_ROUND(13) TF_ROUND(15) TF_ROUND(26) TF_ROUND(6)
    x0 += k1; x1 += k2 + 1u;
    TF_ROUND(17) TF_ROUND(29) TF_ROUND(16) TF_ROUND(24)
    x0 += k2; x1 += k0 + 2u;
    TF_ROUND(13) TF_ROUND(15) TF_ROUND(26) TF_ROUND(6)
    x0 += k0; x1 += k1 + 3u;
    TF_ROUND(17) TF_ROUND(29) TF_ROUND(16) TF_ROUND(24)
    x0 += k1; x1 += k2 + 4u;
    TF_ROUND(13) TF_ROUND(15) TF_ROUND(26) TF_ROUND(6)
    x0 += k2; x1 += k0 + 5u;
#undef TF_ROUND
#undef TF_ROT
    o0 = x0; o1 = x1;
}

// Partitionable threefry bits: element i -> counter (0, i), output o0^o1.
__device__ __forceinline__ unsigned random_bits_partitionable(
    unsigned ka, unsigned kb, unsigned idx)
{
    unsigned o0, o1;
    threefry2x32(ka, kb, 0u, idx, o0, o1);
    return o0 ^ o1;
}

// Fast e = -log(u), rel err < ~1.2e-5 everywhere.
//  u >= 27/32: e = 2*atanh(z), z=(1-u)/(1+u) <= 0.0847 (1-u exact, Sterbenz);
//              p = 1 + y/3, trunc y^2/5 <= 1.04e-5 rel.
//  u <  27/32: e >= 0.1699, __logf abs err ~5e-7 -> rel <= 3e-6.
// u = f-1 without the tiny clamp: u==0 (P=2^-23) gives e=+inf -> r=0; every
// case where that element could matter lands in the exact fallback (thr==0
// or popc!=1), so argmax correctness is unaffected.
__device__ __forceinline__ float e_from_bits(unsigned bits)
{
    unsigned m = (bits >> 9) | 0x3f800000u;
    float u = __uint_as_float(m) - 1.0f;
    float lg = -__logf(u);
    float z = __fdividef(1.0f - u, 1.0f + u);
    float p = fmaf(z * z, 0.33333333333f, 1.0f);
    return (u >= 0.84375f) ? (2.0f * z * p) : lg;
}

// Exact uniform + gumbel (double-evaluated, correctly-rounded f32 chain).
__device__ __forceinline__ float uniform_exact(unsigned bits)
{
    const float tiny = 1.17549435082228750797e-38f;
    unsigned m = (bits >> 9) | 0x3f800000u;
    float u = __uint_as_float(m) - 1.0f;
    u = u + tiny;
    return fmaxf(tiny, u);
}
__device__ __forceinline__ float gumbel_exact(unsigned bits)
{
    float u = uniform_exact(bits);
    float l1 = (float)log((double)u);
    float l2 = (float)log((double)(-l1));
    return -l2;
}

// ---------------------------------------------------------------------------
// Cold path: bit-exact reference recomputation of one step's argmax.
// Lane owns elements d0=2*lane and d0+1. Warp-uniform entry.
// ---------------------------------------------------------------------------
__device__ __noinline__ int exact_argmax(
    float t0, float t1, bool v0, bool v1,
    unsigned ka, unsigned kb, unsigned ebase, int d0)
{
    const float LOG_EPS_EXACT = (float)log((double)EPSf);

    float m = fmaxf(t0, t1);
    #pragma unroll
    for (int o = 16; o; o >>= 1)
        m = fmaxf(m, __shfl_xor_sync(FULLMASK, m, o));
    const float tmax = (m > 0.0f) ? m : 1.0f;

    float ew0 = 0.0f, ew1 = 0.0f;
    if (v0) {
        float s = (float)((double)(t0 - tmax) / (double)0.1f);
        ew0 = (float)exp((double)s);
    }
    if (v1) {
        float s = (float)((double)(t1 - tmax) / (double)0.1f);
        ew1 = (float)exp((double)s);
    }
    double dsum = (double)ew0 + (double)ew1;
    #pragma unroll
    for (int o = 16; o; o >>= 1)
        dsum += __shfl_xor_sync(FULLMASK, dsum, o);
    dsum = __shfl_sync(FULLMASK, dsum, 0);
    const float denom = (float)dsum + EPSf;

    float sc0, sc1;
    {
        float g = gumbel_exact(random_bits_partitionable(ka, kb, ebase));
        float lp;
        if (v0) {
            float p = (float)((double)ew0 / (double)denom);
            lp = (float)log((double)(p + EPSf));
        } else lp = LOG_EPS_EXACT;
        sc0 = lp + g;
    }
    {
        float g = gumbel_exact(random_bits_partitionable(ka, kb, ebase + 1u));
        float lp;
        if (v1) {
            float p = (float)((double)ew1 / (double)denom);
            lp = (float)log((double)(p + EPSf));
        } else lp = LOG_EPS_EXACT;
        sc1 = lp + g;
    }

    float bs; int bix;
    if (sc1 > sc0) { bs = sc1; bix = d0 + 1; }
    else           { bs = sc0; bix = d0; }
    #pragma unroll
    for (int o = 16; o; o >>= 1) {
        float os = __shfl_xor_sync(FULLMASK, bs, o);
        int   oi = __shfl_xor_sync(FULLMASK, bix, o);
        if (os > bs || (os == bs && oi < bix)) { bs = os; bix = oi; }
    }
    return __shfl_sync(FULLMASK, bix, 0);
}

// ---------------------------------------------------------------------------
// Persistent warps, per-walk dynamic fetch (fine granularity = the load
// balancer). Lane L owns elements d=2L, 2L+1 (vector loads).
// nvalid <= 32: rank-compact (threefry_idx, w, t, id) int4 records into a
//               parity-double-buffered smem queue (no WAR sync); ONE
//               threefry per lane; winner (id, t) via one LDS.128.
// nvalid >  32: direct two-threefry path (threefry load-independent).
// ---------------------------------------------------------------------------
__global__ void __launch_bounds__(128, 12)
walk_kernel(const int* __restrict__ src_nodes,
            const float* __restrict__ cur_times,
            const int* __restrict__ nb_ids,
            const float* __restrict__ nb_times,
            float* __restrict__ out,
            int B, StepKeys keys)
{
    __shared__ int4 s_q[4][2][32];  // per-warp, parity double-buffered

    const int lane = (int)(threadIdx.x & 31);
    const int wwarp = (int)(threadIdx.x >> 5);
    const unsigned nwalks = (unsigned)(B * W_WALKS);

    const size_t BWL = (size_t)nwalks * L_STEPS;
    float* const out_nodes = out;
    float* const out_times = out + BWL;
    float* const out_masks = out + 2 * BWL;

    const int d0 = lane << 1;
    unsigned ltmask;
    asm("mov.u32 %0, %%lanemask_lt;" : "=r"(ltmask));

    while (true) {
        // ---- fetch next walk (warp-collective) ----
        unsigned gwarp_u = 0;
        if (lane == 0) gwarp_u = atomicAdd(&g_walk_ctr, 1u);
        gwarp_u = __shfl_sync(FULLMASK, gwarp_u, 0);
        if (gwarp_u >= nwalks) return;
        const int gwarp = (int)gwarp_u;
        const int b = gwarp / W_WALKS;

        int   curr  = src_nodes[b];
        float ctime = cur_times[b];

        const size_t base = (size_t)gwarp * L_STEPS;
        const unsigned ebase64 = (unsigned)gwarp * DNB;
        const unsigned elane0 = ebase64 + (unsigned)d0;   // this lane's idx

        if (lane == 0) {
            out_nodes[base] = (float)curr;
            out_times[base] = ctime;
            out_masks[base] = 1.0f;
        }

        int step = 1;
        #pragma unroll 1
        for (; step < L_STEPS; step++) {
            const unsigned rowo = (unsigned)curr * DNB;  // 32-bit safe
            const int2   ids = reinterpret_cast<const int2*>(nb_ids + rowo)[lane];
            const float2 ts  = reinterpret_cast<const float2*>(nb_times + rowo)[lane];
            const float t0 = ts.x, t1 = ts.y;

            const bool v0 = (t0 < ctime);
            const bool v1 = (t1 < ctime);
            const unsigned bL = __ballot_sync(FULLMASK, v0);
            const unsigned bH = __ballot_sync(FULLMASK, v1);
            const int nvalid = __popc(bL) + __popc(bH);

            if (nvalid == 0) break;   // walk dies; tail flushed below

            const unsigned ka = keys.a[step];
            const unsigned kb = keys.b[step];

            // weights, ctime-centered (warp-uniform frame factor -> argmax-
            // neutral; fp error within guard)
            const float ct14 = ctime * LOG2E10;
            float w0 = v0 ? exp2f(fmaf(t0, LOG2E10, -ct14)) : 0.0f;
            float w1 = v1 ? exp2f(fmaf(t1, LOG2E10, -ct14)) : 0.0f;

            // low-precision warp sum via fixed point + integer REDUX (S is
            // only used for the tiebreak constant c; 2% accuracy is ample).
            const unsigned wi = __float2uint_rn(w0 * FP_SCALE)
                              + __float2uint_rn(w1 * FP_SCALE);
            const float ssum = (float)__reduce_add_sync(FULLMASK, wi) * FP_INV;
            const float c = EPSf * (ssum + EPSf);

            bool resolved = false;
            int bi = -1;   // only meaningful for full/fallback paths

            if (nvalid <= 32) {
                // ---- COMPACTED: rank-scatter full records in element order
                // into the parity buffer (no WAR sync needed); ONE threefry
                // per lane; winner via one LDS.128.
                const int par = step & 1;
                const int rank0 = __popc(bL & ltmask) + __popc(bH & ltmask);
                if (v0) s_q[wwarp][par][rank0] = make_int4(
                    (int)elane0, __float_as_int(w0),
                    __float_as_int(t0), ids.x);
                if (v1) s_q[wwarp][par][rank0 + (v0 ? 1 : 0)] = make_int4(
                    (int)(elane0 + 1u), __float_as_int(w1),
                    __float_as_int(t1), ids.y);
                __syncwarp();   // write -> read ordering fence

                // Unclamped read: lanes >= nvalid see stale data but their
                // r stays 0 (predicated below) — harmless.
                const int4  q  = s_q[wwarp][par][lane];
                const float wd = __int_as_float(q.y);

                float r = 0.0f;
                if (lane < nvalid) {
                    const float e = e_from_bits(random_bits_partitionable(
                        ka, kb, (unsigned)q.x));
                    r = __fdividef(wd + c, e);
                }

                const unsigned bmax = __reduce_max_sync(
                    FULLMASK, __float_as_uint(r));
                const float thr = __uint_as_float(bmax) * (1.0f - REL_GAP);

                const unsigned bb = __ballot_sync(FULLMASK, r >= thr);
                // unique in-band winner AND unscored masked elements provably
                // below the band (r_masked <= c*1e7 incl. S error margin)
                if (__popc(bb) == 1 && thr > c * MASKED_C_MULT) {
                    const int4 qw = s_q[wwarp][par][__ffs(bb) - 1];
                    curr  = qw.w;                      // id
                    ctime = __int_as_float(qw.z);      // t
                    resolved = true;
                }
            } else {
                // ---- FULL: both elements per lane; threefry independent of
                // the gathers (overlaps load latency). Masked elements get
                // r = c/e, exactly the reference surrogate, for free.
                const float e0 = e_from_bits(random_bits_partitionable(
                    ka, kb, elane0));
                const float e1 = e_from_bits(random_bits_partitionable(
                    ka, kb, elane0 + 1u));
                const float r0 = __fdividef(w0 + c, e0);
                const float r1 = __fdividef(w1 + c, e1);

                const unsigned bmax = __reduce_max_sync(
                    FULLMASK, __float_as_uint(fmaxf(r0, r1)));
                const float thr = __uint_as_float(bmax) * (1.0f - REL_GAP);

                const unsigned bb0 = __ballot_sync(FULLMASK, r0 >= thr);
                const unsigned bb1 = __ballot_sync(FULLMASK, r1 >= thr);
                if (__popc(bb0) + __popc(bb1) == 1)
                    bi = bb0 ? ((__ffs(bb0) - 1) << 1)
                             : (((__ffs(bb1) - 1) << 1) | 1);
            }

            if (!resolved) {
                if (bi < 0)  // warp-uniform: guard failed -> bit-exact path
                    bi = exact_argmax(t0, t1, v0, v1, ka, kb, elane0, d0);

                // fetch chosen neighbor from its owner lane (bi uniform)
                const int slot = (bi & 1);
                curr  = __shfl_sync(FULLMASK, slot ? ids.y : ids.x, bi >> 1);
                ctime = __shfl_sync(FULLMASK, slot ? t1    : t0,   bi >> 1);
            }

            if (lane == 0) {
                out_nodes[base + step] = (float)curr;
                out_times[base + step] = ctime;
                out_masks[base + step] = 1.0f;
            }
        }

        // dead-walk tail: sticky values, mask 0
        if (lane == 0) {
            for (int s2 = step; s2 < L_STEPS; s2++) {
                out_nodes[base + s2] = (float)curr;
                out_times[base + s2] = ctime;
                out_masks[base + s2] = 0.0f;
            }
        }
    }
}

// ---------------------------------------------------------------------------
extern "C" void kernel_launch(void* const* d_in, const int* in_sizes, int n_in,
                              void* d_out, int out_size)
{
    const int*   src = (const int*)d_in[0];
    const float* ct  = (const float*)d_in[1];
    const int*   nid = (const int*)d_in[2];
    const float* nt  = (const float*)d_in[3];
    const int B = in_sizes[0];

    // fold_in(key(42), step) = threefry2x32((0,42), (0,step))
    StepKeys keys;
    for (int s = 0; s < L_STEPS; s++) { keys.a[s] = 0; keys.b[s] = 0; }
    for (int s = 1; s < L_STEPS; s++) {
        unsigned o0, o1;
        threefry2x32(0u, 42u, 0u, (unsigned)s, o0, o1);
        keys.a[s] = o0; keys.b[s] = o1;
    }

    // Persistent grid: 12 blocks/SM x 152 SMs. Extra blocks are harmless
    // (they exit when the queue is empty).
    reset_ctr_kernel<<<1, 1>>>();
    walk_kernel<<<1824, 128>>>(src, ct, nid, nt, (float*)d_out, B, keys);
}